// round 12
// baseline (speedup 1.0000x reference)
#include <cuda_runtime.h>
#include <stdint.h>
#include <math.h>

#define Bb 512
#define Nn 1024
#define Pp 1024
#define Kk 1024
#define Tt 32
#define EPSV 1e-10f

// scratch (no allocations allowed)
__device__ float g_a[Bb * Nn];      // relu activations [B,N]
__device__ float g_asigT[Nn * Bb];  // sigmoid activations, transposed [N,B]
__device__ float g_acc[4];          // 0: recon sq-sum, 1: entropy, 2: decay

// ---------------------------------------------------------------------------
// GEMM1: a = relu(x @ w_enc + b_enc); a_sigT scattered store
// tile M=64 x N=32, 128 threads, 4x4 per thread, BK=16, register prefetch
// grid (Nn/32, Bb/64) = (32, 8) = 256 CTAs
// ---------------------------------------------------------------------------
__global__ __launch_bounds__(128) void gemm_enc(const float* __restrict__ X,
                                                const float* __restrict__ W,
                                                const float* __restrict__ bias) {
    __shared__ __align__(16) float As[16][68];
    __shared__ __align__(16) float Bs[16][36];
    int t = threadIdx.x;
    if (blockIdx.x == 0 && blockIdx.y == 0 && t < 4) g_acc[t] = 0.f;
    int m0 = blockIdx.y * 64, n0 = blockIdx.x * 32;
    int arow = t >> 2, acol = (t & 3) << 2;   // A chunk0: rows 0..31; chunk1: +32
    int brow = t >> 3, bcol = (t & 7) << 2;   // B: 16 k-rows x 32 n
    int ry = (t >> 3) << 2, rx = (t & 7) << 2;
    float acc[4][4] = {};
    const float* ap = X + (size_t)m0 * Kk;
    const float* bp = W + n0;
    float4 av0 = *(const float4*)(ap + (size_t)arow * Kk + acol);
    float4 av1 = *(const float4*)(ap + (size_t)(arow + 32) * Kk + acol);
    float4 bv  = *(const float4*)(bp + (size_t)brow * Nn + bcol);
    for (int k0 = 0; k0 < Kk; k0 += 16) {
        __syncthreads();
        As[acol + 0][arow] = av0.x; As[acol + 1][arow] = av0.y;
        As[acol + 2][arow] = av0.z; As[acol + 3][arow] = av0.w;
        As[acol + 0][arow + 32] = av1.x; As[acol + 1][arow + 32] = av1.y;
        As[acol + 2][arow + 32] = av1.z; As[acol + 3][arow + 32] = av1.w;
        *(float4*)(&Bs[brow][bcol]) = bv;
        __syncthreads();
        if (k0 + 16 < Kk) {
            av0 = *(const float4*)(ap + (size_t)arow * Kk + k0 + 16 + acol);
            av1 = *(const float4*)(ap + (size_t)(arow + 32) * Kk + k0 + 16 + acol);
            bv  = *(const float4*)(bp + (size_t)(k0 + 16 + brow) * Nn + bcol);
        }
#pragma unroll
        for (int k = 0; k < 16; k++) {
            float4 a4 = *(float4*)(&As[k][ry]);
            float4 b4 = *(float4*)(&Bs[k][rx]);
            float am[4] = {a4.x, a4.y, a4.z, a4.w};
            float bn[4] = {b4.x, b4.y, b4.z, b4.w};
#pragma unroll
            for (int i = 0; i < 4; i++)
#pragma unroll
                for (int j = 0; j < 4; j++)
                    acc[i][j] = fmaf(am[i], bn[j], acc[i][j]);
        }
    }
    float4 b4 = *(const float4*)(bias + n0 + rx);
    float bb[4] = {b4.x, b4.y, b4.z, b4.w};
#pragma unroll
    for (int i = 0; i < 4; i++) {
        int m = m0 + ry + i;
        float aa[4];
#pragma unroll
        for (int j = 0; j < 4; j++) {
            float v = acc[i][j] + bb[j];
            float a = fmaxf(v, 0.f);
            aa[j] = a;
            float e = __expf(-a);
            g_asigT[(size_t)(n0 + rx + j) * Bb + m] = __fdividef(2.f, 1.f + e) - 1.f;
        }
        *(float4*)(g_a + (size_t)m * Nn + n0 + rx) =
            make_float4(aa[0], aa[1], aa[2], aa[3]);
    }
}

// ---------------------------------------------------------------------------
// GEMM2: x_hat = a @ w_dec + b_dec ; accumulate sum((x-x_hat)^2)
// ---------------------------------------------------------------------------
__global__ __launch_bounds__(128) void gemm_dec(const float* __restrict__ W,
                                                const float* __restrict__ bias,
                                                const float* __restrict__ X,
                                                float* __restrict__ xhat) {
    __shared__ __align__(16) float As[16][68];
    __shared__ __align__(16) float Bs[16][36];
    int t = threadIdx.x;
    int m0 = blockIdx.y * 64, n0 = blockIdx.x * 32;
    int arow = t >> 2, acol = (t & 3) << 2;
    int brow = t >> 3, bcol = (t & 7) << 2;
    int ry = (t >> 3) << 2, rx = (t & 7) << 2;
    float acc[4][4] = {};
    const float* ap = g_a + (size_t)m0 * Nn;
    const float* bp = W + n0;
    float4 av0 = *(const float4*)(ap + (size_t)arow * Nn + acol);
    float4 av1 = *(const float4*)(ap + (size_t)(arow + 32) * Nn + acol);
    float4 bv  = *(const float4*)(bp + (size_t)brow * Pp + bcol);
    for (int k0 = 0; k0 < Nn; k0 += 16) {
        __syncthreads();
        As[acol + 0][arow] = av0.x; As[acol + 1][arow] = av0.y;
        As[acol + 2][arow] = av0.z; As[acol + 3][arow] = av0.w;
        As[acol + 0][arow + 32] = av1.x; As[acol + 1][arow + 32] = av1.y;
        As[acol + 2][arow + 32] = av1.z; As[acol + 3][arow + 32] = av1.w;
        *(float4*)(&Bs[brow][bcol]) = bv;
        __syncthreads();
        if (k0 + 16 < Nn) {
            av0 = *(const float4*)(ap + (size_t)arow * Nn + k0 + 16 + acol);
            av1 = *(const float4*)(ap + (size_t)(arow + 32) * Nn + k0 + 16 + acol);
            bv  = *(const float4*)(bp + (size_t)(k0 + 16 + brow) * Pp + bcol);
        }
#pragma unroll
        for (int k = 0; k < 16; k++) {
            float4 a4 = *(float4*)(&As[k][ry]);
            float4 b4 = *(float4*)(&Bs[k][rx]);
            float am[4] = {a4.x, a4.y, a4.z, a4.w};
            float bn[4] = {b4.x, b4.y, b4.z, b4.w};
#pragma unroll
            for (int i = 0; i < 4; i++)
#pragma unroll
                for (int j = 0; j < 4; j++)
                    acc[i][j] = fmaf(am[i], bn[j], acc[i][j]);
        }
    }
    float lsum = 0.f;
    float4 b4 = *(const float4*)(bias + n0 + rx);
    float bb[4] = {b4.x, b4.y, b4.z, b4.w};
#pragma unroll
    for (int i = 0; i < 4; i++) {
        int m = m0 + ry + i;
        float4 xv = *(const float4*)(X + (size_t)m * Pp + n0 + rx);
        float xm[4] = {xv.x, xv.y, xv.z, xv.w};
        float vv[4];
#pragma unroll
        for (int j = 0; j < 4; j++) {
            float v = acc[i][j] + bb[j];
            vv[j] = v;
            float d = xm[j] - v;
            lsum = fmaf(d, d, lsum);
        }
        *(float4*)(xhat + (size_t)m * Pp + n0 + rx) =
            make_float4(vv[0], vv[1], vv[2], vv[3]);
    }
#pragma unroll
    for (int o = 16; o > 0; o >>= 1) lsum += __shfl_xor_sync(~0u, lsum, o);
    __shared__ float red[4];
    if ((t & 31) == 0) red[t >> 5] = lsum;
    __syncthreads();
    if (t == 0) atomicAdd(&g_acc[0], red[0] + red[1] + red[2] + red[3]);
}

// ---------------------------------------------------------------------------
// MLE: per-neuron 15-step gradient ascent on thetas + entropy (unchanged,
// proven at 203us lineage)
// ---------------------------------------------------------------------------
__global__ __launch_bounds__(128) void mle_kernel(const float* __restrict__ thetas,
                                                  const float* __restrict__ centers,
                                                  float* __restrict__ ent_out) {
    __shared__ float s_pi[4][32];
    __shared__ float s_G[4][4 * 33];
    __shared__ float s_c[32];
    int tid = threadIdx.x;
    int warp = tid >> 5, lane = tid & 31;
    if (tid < 32) s_c[tid] = centers[tid];
    __syncthreads();
    int n = blockIdx.x * 4 + warp;
    float c0 = s_c[0];
    float invw = __fdividef(1.0f, s_c[1] - s_c[0]);

    const float* col = g_asigT + (size_t)n * Bb;
    int t0[16];
    float w0[16], w1[16];
    unsigned zbits = 0, obits = 0;
    int zc = 0, oc = 0;
#pragma unroll
    for (int i = 0; i < 16; i++) {
        float as = col[i * 32 + lane];
        if (as == 0.f) { zbits |= 1u << i; zc++; }
        else if (as == 1.f) { obits |= 1u << i; oc++; }
        float xf = (as - c0) * invw;
        int tt = (int)floorf(xf);
        tt = min(max(tt, 0), 30);
        t0[i] = tt;
        w0[i] = fmaxf(0.f, 1.f - fabsf(as - s_c[tt]) * invw);
        w1[i] = fmaxf(0.f, 1.f - fabsf(as - s_c[tt + 1]) * invw);
    }
    int ztot = zc, otot = oc;
#pragma unroll
    for (int o = 16; o > 0; o >>= 1) {
        ztot += __shfl_xor_sync(~0u, ztot, o);
        otot += __shfl_xor_sync(~0u, otot, o);
    }
    float w0z = fmaxf(0.f, 1.f - fabsf(s_c[15]) * invw);
    float w1z = fmaxf(0.f, 1.f - fabsf(s_c[16]) * invw);
    float w0o = fmaxf(0.f, 1.f - fabsf(1.f - s_c[30]) * invw);
    float w1o = fmaxf(0.f, 1.f - fabsf(1.f - s_c[31]) * invw);
    float zf = (float)ztot, of = (float)otot;

    float th = thetas[n * Tt + lane];
    float* pi = s_pi[warp];
    float* G = s_G[warp];
    int rep = (lane & 3) * 33;
    unsigned skip = zbits | obits;

    for (int step = 0; step < 15; step++) {
        float m = th;
#pragma unroll
        for (int o = 16; o > 0; o >>= 1) m = fmaxf(m, __shfl_xor_sync(~0u, m, o));
        float e = __expf(th - m);
        float sum = e;
#pragma unroll
        for (int o = 16; o > 0; o >>= 1) sum += __shfl_xor_sync(~0u, sum, o);
        float p_l = __fdividef(e, sum);
        pi[lane] = p_l;
        G[0 * 33 + lane] = 0.f; G[1 * 33 + lane] = 0.f;
        G[2 * 33 + lane] = 0.f; G[3 * 33 + lane] = 0.f;
        __syncwarp();

        float s_acc = 0.f;
        if (lane == 0 && ztot > 0) {
            float pz = w0z * pi[15] + w1z * pi[16];
            float rz = __fdividef(1.f, pz + EPSV);
            atomicAdd(&G[0 * 33 + 15], zf * w0z * rz);
            atomicAdd(&G[0 * 33 + 16], zf * w1z * rz);
            s_acc += zf * pz * rz;
        }
        if (lane == 1 && otot > 0) {
            float po = w0o * pi[30] + w1o * pi[31];
            float ro = __fdividef(1.f, po + EPSV);
            atomicAdd(&G[1 * 33 + 30], of * w0o * ro);
            atomicAdd(&G[1 * 33 + 31], of * w1o * ro);
            s_acc += of * po * ro;
        }
#pragma unroll
        for (int i = 0; i < 16; i++) {
            if (!((skip >> i) & 1u)) {
                float p = w0[i] * pi[t0[i]] + w1[i] * pi[t0[i] + 1];
                float r = __fdividef(1.f, p + EPSV);
                atomicAdd(&G[rep + t0[i]], w0[i] * r);
                atomicAdd(&G[rep + t0[i] + 1], w1[i] * r);
                s_acc = fmaf(p, r, s_acc);
            }
        }
#pragma unroll
        for (int o = 16; o > 0; o >>= 1) s_acc += __shfl_xor_sync(~0u, s_acc, o);
        __syncwarp();
        float g = G[0 * 33 + lane] + G[1 * 33 + lane] +
                  G[2 * 33 + lane] + G[3 * 33 + lane];
        th += 0.01f * (p_l * (g - s_acc));
        __syncwarp();
    }

    float m = th;
#pragma unroll
    for (int o = 16; o > 0; o >>= 1) m = fmaxf(m, __shfl_xor_sync(~0u, m, o));
    float e = __expf(th - m);
    float sum = e;
#pragma unroll
    for (int o = 16; o > 0; o >>= 1) sum += __shfl_xor_sync(~0u, sum, o);
    pi[lane] = __fdividef(e, sum);
    __syncwarp();

    float ent = 0.f;
    if (lane == 0 && ztot > 0) {
        float pz = w0z * pi[15] + w1z * pi[16];
        ent -= zf * pz * __logf(pz + EPSV);
    }
    if (lane == 1 && otot > 0) {
        float po = w0o * pi[30] + w1o * pi[31];
        ent -= of * po * __logf(po + EPSV);
    }
#pragma unroll
    for (int i = 0; i < 16; i++) {
        if (!((skip >> i) & 1u)) {
            float p = w0[i] * pi[t0[i]] + w1[i] * pi[t0[i] + 1];
            ent -= p * __logf(p + EPSV);
        }
    }
#pragma unroll
    for (int o = 16; o > 0; o >>= 1) ent += __shfl_xor_sync(~0u, ent, o);
    if (lane == 0) {
        ent_out[n] = ent;
        atomicAdd(&g_acc[1], ent);
    }
}

// ---------------------------------------------------------------------------
// decay: sum(w_enc^2) + sum(w_dec^2), vectorized, big grid
// ---------------------------------------------------------------------------
__global__ __launch_bounds__(256) void decay_kernel(const float* __restrict__ we,
                                                    const float* __restrict__ wd) {
    float s = 0.f;
    const float4* we4 = (const float4*)we;
    const float4* wd4 = (const float4*)wd;
    int nv = (Nn * Pp) / 4;
    for (int i = blockIdx.x * blockDim.x + threadIdx.x; i < nv;
         i += gridDim.x * blockDim.x) {
        float4 a = we4[i];
        s = fmaf(a.x, a.x, s); s = fmaf(a.y, a.y, s);
        s = fmaf(a.z, a.z, s); s = fmaf(a.w, a.w, s);
        float4 b = wd4[i];
        s = fmaf(b.x, b.x, s); s = fmaf(b.y, b.y, s);
        s = fmaf(b.z, b.z, s); s = fmaf(b.w, b.w, s);
    }
#pragma unroll
    for (int o = 16; o > 0; o >>= 1) s += __shfl_xor_sync(~0u, s, o);
    __shared__ float red[8];
    if ((threadIdx.x & 31) == 0) red[threadIdx.x >> 5] = s;
    __syncthreads();
    if (threadIdx.x == 0) {
        float tot = 0.f;
#pragma unroll
        for (int i = 0; i < 8; i++) tot += red[i];
        atomicAdd(&g_acc[2], tot);
    }
}

__global__ void finalize_kernel(float* __restrict__ out) {
    out[Bb * Pp + Nn] = (0.5f / (float)Bb) * g_acc[0] + 0.01f * g_acc[1] +
                        0.00025f * g_acc[2];
}

extern "C" void kernel_launch(void* const* d_in, const int* in_sizes, int n_in,
                              void* d_out, int out_size) {
    const float* x   = (const float*)d_in[0];
    const float* we  = (const float*)d_in[1];
    const float* be  = (const float*)d_in[2];
    const float* wd  = (const float*)d_in[3];
    const float* bd  = (const float*)d_in[4];
    const float* th  = (const float*)d_in[5];
    const float* cen = (const float*)d_in[6];
    float* out = (float*)d_out;

    gemm_enc<<<dim3(Nn / 32, Bb / 64), 128>>>(x, we, be);
    mle_kernel<<<Nn / 4, 128>>>(th, cen, out + Bb * Pp);
    decay_kernel<<<1024, 256>>>(we, wd);
    gemm_dec<<<dim3(Pp / 32, Bb / 64), 128>>>(wd, bd, x, out);
    finalize_kernel<<<1, 1>>>(out);
}

// round 13
// speedup vs baseline: 1.0443x; 1.0443x over previous
#include <cuda_runtime.h>
#include <stdint.h>
#include <math.h>

#define Bb 512
#define Nn 1024
#define Pp 1024
#define Kk 1024
#define Tt 32
#define EPSV 1e-10f

#define DEC_BLOCKS 256   // (Pp/32) * (Bb/64)
#define MLE_BLOCKS 256   // Nn / 4
#define DECAY_BLOCKS 64
#define PH2_BLOCKS (DEC_BLOCKS + MLE_BLOCKS + DECAY_BLOCKS)

// scratch (no allocations allowed)
__device__ float g_a[Bb * Nn];      // relu activations [B,N]
__device__ float g_asigT[Nn * Bb];  // sigmoid activations, transposed [N,B]
__device__ float g_acc[4];          // 0: recon sq-sum, 1: entropy, 2: decay

// ---------------------------------------------------------------------------
// GEMM1: a = relu(x @ w_enc + b_enc); a_sigT scattered store
// tile M=64 x N=32, 128 threads, 4x4 per thread, BK=16, register prefetch
// ---------------------------------------------------------------------------
__global__ __launch_bounds__(128) void gemm_enc(const float* __restrict__ X,
                                                const float* __restrict__ W,
                                                const float* __restrict__ bias) {
    __shared__ __align__(16) float As[16][68];
    __shared__ __align__(16) float Bs[16][36];
    int t = threadIdx.x;
    if (blockIdx.x == 0 && blockIdx.y == 0 && t < 4) g_acc[t] = 0.f;
    int m0 = blockIdx.y * 64, n0 = blockIdx.x * 32;
    int arow = t >> 2, acol = (t & 3) << 2;
    int brow = t >> 3, bcol = (t & 7) << 2;
    int ry = (t >> 3) << 2, rx = (t & 7) << 2;
    float acc[4][4] = {};
    const float* ap = X + (size_t)m0 * Kk;
    const float* bp = W + n0;
    float4 av0 = *(const float4*)(ap + (size_t)arow * Kk + acol);
    float4 av1 = *(const float4*)(ap + (size_t)(arow + 32) * Kk + acol);
    float4 bv  = *(const float4*)(bp + (size_t)brow * Nn + bcol);
    for (int k0 = 0; k0 < Kk; k0 += 16) {
        __syncthreads();
        As[acol + 0][arow] = av0.x; As[acol + 1][arow] = av0.y;
        As[acol + 2][arow] = av0.z; As[acol + 3][arow] = av0.w;
        As[acol + 0][arow + 32] = av1.x; As[acol + 1][arow + 32] = av1.y;
        As[acol + 2][arow + 32] = av1.z; As[acol + 3][arow + 32] = av1.w;
        *(float4*)(&Bs[brow][bcol]) = bv;
        __syncthreads();
        if (k0 + 16 < Kk) {
            av0 = *(const float4*)(ap + (size_t)arow * Kk + k0 + 16 + acol);
            av1 = *(const float4*)(ap + (size_t)(arow + 32) * Kk + k0 + 16 + acol);
            bv  = *(const float4*)(bp + (size_t)(k0 + 16 + brow) * Nn + bcol);
        }
#pragma unroll
        for (int k = 0; k < 16; k++) {
            float4 a4 = *(float4*)(&As[k][ry]);
            float4 b4 = *(float4*)(&Bs[k][rx]);
            float am[4] = {a4.x, a4.y, a4.z, a4.w};
            float bn[4] = {b4.x, b4.y, b4.z, b4.w};
#pragma unroll
            for (int i = 0; i < 4; i++)
#pragma unroll
                for (int j = 0; j < 4; j++)
                    acc[i][j] = fmaf(am[i], bn[j], acc[i][j]);
        }
    }
    float4 b4 = *(const float4*)(bias + n0 + rx);
    float bb[4] = {b4.x, b4.y, b4.z, b4.w};
#pragma unroll
    for (int i = 0; i < 4; i++) {
        int m = m0 + ry + i;
        float aa[4];
#pragma unroll
        for (int j = 0; j < 4; j++) {
            float v = acc[i][j] + bb[j];
            float a = fmaxf(v, 0.f);
            aa[j] = a;
            float e = __expf(-a);
            g_asigT[(size_t)(n0 + rx + j) * Bb + m] = __fdividef(2.f, 1.f + e) - 1.f;
        }
        *(float4*)(g_a + (size_t)m * Nn + n0 + rx) =
            make_float4(aa[0], aa[1], aa[2], aa[3]);
    }
}

// ---------------------------------------------------------------------------
// phase2 bodies (device functions sharing one smem buffer)
// ---------------------------------------------------------------------------
__device__ __forceinline__ void dec_body(int bx, char* shm,
                                         const float* __restrict__ W,
                                         const float* __restrict__ bias,
                                         const float* __restrict__ X,
                                         float* __restrict__ xhat) {
    float (*As)[68] = (float (*)[68])shm;                 // 16*68*4 = 4352
    float (*Bs)[36] = (float (*)[36])(shm + 4352);        // 16*36*4 = 2304
    float* red = (float*)(shm + 6656);                    // 16 B
    int t = threadIdx.x;
    int m0 = (bx >> 5) * 64, n0 = (bx & 31) * 32;
    int arow = t >> 2, acol = (t & 3) << 2;
    int brow = t >> 3, bcol = (t & 7) << 2;
    int ry = (t >> 3) << 2, rx = (t & 7) << 2;
    float acc[4][4] = {};
    const float* ap = g_a + (size_t)m0 * Nn;
    const float* bp = W + n0;
    float4 av0 = *(const float4*)(ap + (size_t)arow * Nn + acol);
    float4 av1 = *(const float4*)(ap + (size_t)(arow + 32) * Nn + acol);
    float4 bv  = *(const float4*)(bp + (size_t)brow * Pp + bcol);
    for (int k0 = 0; k0 < Nn; k0 += 16) {
        __syncthreads();
        As[acol + 0][arow] = av0.x; As[acol + 1][arow] = av0.y;
        As[acol + 2][arow] = av0.z; As[acol + 3][arow] = av0.w;
        As[acol + 0][arow + 32] = av1.x; As[acol + 1][arow + 32] = av1.y;
        As[acol + 2][arow + 32] = av1.z; As[acol + 3][arow + 32] = av1.w;
        *(float4*)(&Bs[brow][bcol]) = bv;
        __syncthreads();
        if (k0 + 16 < Nn) {
            av0 = *(const float4*)(ap + (size_t)arow * Nn + k0 + 16 + acol);
            av1 = *(const float4*)(ap + (size_t)(arow + 32) * Nn + k0 + 16 + acol);
            bv  = *(const float4*)(bp + (size_t)(k0 + 16 + brow) * Pp + bcol);
        }
#pragma unroll
        for (int k = 0; k < 16; k++) {
            float4 a4 = *(float4*)(&As[k][ry]);
            float4 b4 = *(float4*)(&Bs[k][rx]);
            float am[4] = {a4.x, a4.y, a4.z, a4.w};
            float bn[4] = {b4.x, b4.y, b4.z, b4.w};
#pragma unroll
            for (int i = 0; i < 4; i++)
#pragma unroll
                for (int j = 0; j < 4; j++)
                    acc[i][j] = fmaf(am[i], bn[j], acc[i][j]);
        }
    }
    float lsum = 0.f;
    float4 b4 = *(const float4*)(bias + n0 + rx);
    float bb[4] = {b4.x, b4.y, b4.z, b4.w};
#pragma unroll
    for (int i = 0; i < 4; i++) {
        int m = m0 + ry + i;
        float4 xv = *(const float4*)(X + (size_t)m * Pp + n0 + rx);
        float xm[4] = {xv.x, xv.y, xv.z, xv.w};
        float vv[4];
#pragma unroll
        for (int j = 0; j < 4; j++) {
            float v = acc[i][j] + bb[j];
            vv[j] = v;
            float d = xm[j] - v;
            lsum = fmaf(d, d, lsum);
        }
        *(float4*)(xhat + (size_t)m * Pp + n0 + rx) =
            make_float4(vv[0], vv[1], vv[2], vv[3]);
    }
#pragma unroll
    for (int o = 16; o > 0; o >>= 1) lsum += __shfl_xor_sync(~0u, lsum, o);
    if ((t & 31) == 0) red[t >> 5] = lsum;
    __syncthreads();
    if (t == 0) atomicAdd(&g_acc[0], red[0] + red[1] + red[2] + red[3]);
}

__device__ __forceinline__ void mle_body(int bx, char* shm,
                                         const float* __restrict__ thetas,
                                         const float* __restrict__ centers,
                                         float* __restrict__ ent_out) {
    float (*s_pi)[32] = (float (*)[32])shm;                // 512 B
    float (*s_G)[132] = (float (*)[132])(shm + 512);       // 2112 B
    float* s_c = (float*)(shm + 2624);                     // 128 B
    int tid = threadIdx.x;
    int warp = tid >> 5, lane = tid & 31;
    if (tid < 32) s_c[tid] = centers[tid];
    __syncthreads();
    int n = bx * 4 + warp;
    float c0 = s_c[0];
    float invw = __fdividef(1.0f, s_c[1] - s_c[0]);

    const float* col = g_asigT + (size_t)n * Bb;
    int t0[16];
    float w0[16], w1[16];
    unsigned zbits = 0, obits = 0;
    int zc = 0, oc = 0;
#pragma unroll
    for (int i = 0; i < 16; i++) {
        float as = col[i * 32 + lane];
        if (as == 0.f) { zbits |= 1u << i; zc++; }
        else if (as == 1.f) { obits |= 1u << i; oc++; }
        float xf = (as - c0) * invw;
        int tt = (int)floorf(xf);
        tt = min(max(tt, 0), 30);
        t0[i] = tt;
        w0[i] = fmaxf(0.f, 1.f - fabsf(as - s_c[tt]) * invw);
        w1[i] = fmaxf(0.f, 1.f - fabsf(as - s_c[tt + 1]) * invw);
    }
    int ztot = zc, otot = oc;
#pragma unroll
    for (int o = 16; o > 0; o >>= 1) {
        ztot += __shfl_xor_sync(~0u, ztot, o);
        otot += __shfl_xor_sync(~0u, otot, o);
    }
    float w0z = fmaxf(0.f, 1.f - fabsf(s_c[15]) * invw);
    float w1z = fmaxf(0.f, 1.f - fabsf(s_c[16]) * invw);
    float w0o = fmaxf(0.f, 1.f - fabsf(1.f - s_c[30]) * invw);
    float w1o = fmaxf(0.f, 1.f - fabsf(1.f - s_c[31]) * invw);
    float zf = (float)ztot, of = (float)otot;

    float th = thetas[n * Tt + lane];
    float* pi = s_pi[warp];
    float* G = s_G[warp];
    int rep = (lane & 3) * 33;
    unsigned skip = zbits | obits;

    for (int step = 0; step < 15; step++) {
        float m = th;
#pragma unroll
        for (int o = 16; o > 0; o >>= 1) m = fmaxf(m, __shfl_xor_sync(~0u, m, o));
        float e = __expf(th - m);
        float sum = e;
#pragma unroll
        for (int o = 16; o > 0; o >>= 1) sum += __shfl_xor_sync(~0u, sum, o);
        float p_l = __fdividef(e, sum);
        pi[lane] = p_l;
        G[0 * 33 + lane] = 0.f; G[1 * 33 + lane] = 0.f;
        G[2 * 33 + lane] = 0.f; G[3 * 33 + lane] = 0.f;
        __syncwarp();

        float s_acc = 0.f;
        if (lane == 0 && ztot > 0) {
            float pz = w0z * pi[15] + w1z * pi[16];
            float rz = __fdividef(1.f, pz + EPSV);
            atomicAdd(&G[0 * 33 + 15], zf * w0z * rz);
            atomicAdd(&G[0 * 33 + 16], zf * w1z * rz);
            s_acc += zf * pz * rz;
        }
        if (lane == 1 && otot > 0) {
            float po = w0o * pi[30] + w1o * pi[31];
            float ro = __fdividef(1.f, po + EPSV);
            atomicAdd(&G[1 * 33 + 30], of * w0o * ro);
            atomicAdd(&G[1 * 33 + 31], of * w1o * ro);
            s_acc += of * po * ro;
        }
#pragma unroll
        for (int i = 0; i < 16; i++) {
            if (!((skip >> i) & 1u)) {
                float p = w0[i] * pi[t0[i]] + w1[i] * pi[t0[i] + 1];
                float r = __fdividef(1.f, p + EPSV);
                atomicAdd(&G[rep + t0[i]], w0[i] * r);
                atomicAdd(&G[rep + t0[i] + 1], w1[i] * r);
                s_acc = fmaf(p, r, s_acc);
            }
        }
#pragma unroll
        for (int o = 16; o > 0; o >>= 1) s_acc += __shfl_xor_sync(~0u, s_acc, o);
        __syncwarp();
        float g = G[0 * 33 + lane] + G[1 * 33 + lane] +
                  G[2 * 33 + lane] + G[3 * 33 + lane];
        th += 0.01f * (p_l * (g - s_acc));
        __syncwarp();
    }

    float m = th;
#pragma unroll
    for (int o = 16; o > 0; o >>= 1) m = fmaxf(m, __shfl_xor_sync(~0u, m, o));
    float e = __expf(th - m);
    float sum = e;
#pragma unroll
    for (int o = 16; o > 0; o >>= 1) sum += __shfl_xor_sync(~0u, sum, o);
    pi[lane] = __fdividef(e, sum);
    __syncwarp();

    float ent = 0.f;
    if (lane == 0 && ztot > 0) {
        float pz = w0z * pi[15] + w1z * pi[16];
        ent -= zf * pz * __logf(pz + EPSV);
    }
    if (lane == 1 && otot > 0) {
        float po = w0o * pi[30] + w1o * pi[31];
        ent -= of * po * __logf(po + EPSV);
    }
#pragma unroll
    for (int i = 0; i < 16; i++) {
        if (!((skip >> i) & 1u)) {
            float p = w0[i] * pi[t0[i]] + w1[i] * pi[t0[i] + 1];
            ent -= p * __logf(p + EPSV);
        }
    }
#pragma unroll
    for (int o = 16; o > 0; o >>= 1) ent += __shfl_xor_sync(~0u, ent, o);
    if (lane == 0) {
        ent_out[n] = ent;
        atomicAdd(&g_acc[1], ent);
    }
}

__device__ __forceinline__ void decay_body(int bx, char* shm,
                                           const float* __restrict__ we,
                                           const float* __restrict__ wd) {
    float* red = (float*)shm;
    float s = 0.f;
    const float4* we4 = (const float4*)we;
    const float4* wd4 = (const float4*)wd;
    int nv = (Nn * Pp) / 4;
    for (int i = bx * 128 + threadIdx.x; i < nv; i += DECAY_BLOCKS * 128) {
        float4 a = we4[i];
        s = fmaf(a.x, a.x, s); s = fmaf(a.y, a.y, s);
        s = fmaf(a.z, a.z, s); s = fmaf(a.w, a.w, s);
        float4 b = wd4[i];
        s = fmaf(b.x, b.x, s); s = fmaf(b.y, b.y, s);
        s = fmaf(b.z, b.z, s); s = fmaf(b.w, b.w, s);
    }
#pragma unroll
    for (int o = 16; o > 0; o >>= 1) s += __shfl_xor_sync(~0u, s, o);
    if ((threadIdx.x & 31) == 0) red[threadIdx.x >> 5] = s;
    __syncthreads();
    if (threadIdx.x == 0)
        atomicAdd(&g_acc[2], red[0] + red[1] + red[2] + red[3]);
}

// ---------------------------------------------------------------------------
// phase2: fused dec-GEMM + MLE + decay (all depend only on gemm_enc outputs,
// mutually independent -> co-resident instead of serial launches)
// ---------------------------------------------------------------------------
__global__ __launch_bounds__(128) void phase2(const float* __restrict__ wd,
                                              const float* __restrict__ bd,
                                              const float* __restrict__ x,
                                              float* __restrict__ xhat,
                                              const float* __restrict__ thetas,
                                              const float* __restrict__ centers,
                                              float* __restrict__ ent_out,
                                              const float* __restrict__ we) {
    __shared__ __align__(16) char shm[6784];
    int bx = blockIdx.x;
    if (bx < DEC_BLOCKS) {
        dec_body(bx, shm, wd, bd, x, xhat);
    } else if (bx < DEC_BLOCKS + MLE_BLOCKS) {
        mle_body(bx - DEC_BLOCKS, shm, thetas, centers, ent_out);
    } else {
        decay_body(bx - DEC_BLOCKS - MLE_BLOCKS, shm, we, wd);
    }
}

__global__ void finalize_kernel(float* __restrict__ out) {
    out[Bb * Pp + Nn] = (0.5f / (float)Bb) * g_acc[0] + 0.01f * g_acc[1] +
                        0.00025f * g_acc[2];
}

extern "C" void kernel_launch(void* const* d_in, const int* in_sizes, int n_in,
                              void* d_out, int out_size) {
    const float* x   = (const float*)d_in[0];
    const float* we  = (const float*)d_in[1];
    const float* be  = (const float*)d_in[2];
    const float* wd  = (const float*)d_in[3];
    const float* bd  = (const float*)d_in[4];
    const float* th  = (const float*)d_in[5];
    const float* cen = (const float*)d_in[6];
    float* out = (float*)d_out;

    gemm_enc<<<dim3(Nn / 32, Bb / 64), 128>>>(x, we, be);
    phase2<<<PH2_BLOCKS, 128>>>(wd, bd, x, out, th, cen, out + Bb * Pp, we);
    finalize_kernel<<<1, 1>>>(out);
}

// round 14
// speedup vs baseline: 1.5203x; 1.4558x over previous
#include <cuda_runtime.h>
#include <stdint.h>
#include <math.h>

#define Bb 512
#define Nn 1024
#define Pp 1024
#define Kk 1024
#define Tt 32
#define EPSV 1e-10f

#define DEC_BLOCKS 256    // (Pp/32) * (Bb/64)
#define MLE_BLOCKS 1024   // one block per neuron
#define DECAY_BLOCKS 64
#define PH2_BLOCKS (DEC_BLOCKS + MLE_BLOCKS + DECAY_BLOCKS)

// scratch (no allocations allowed)
__device__ float g_a[Bb * Nn];      // relu activations [B,N]
__device__ float g_asigT[Nn * Bb];  // sigmoid activations, transposed [N,B]
__device__ float g_acc[4];          // 0: recon sq-sum, 1: entropy, 2: decay

// ---------------------------------------------------------------------------
// GEMM1: a = relu(x @ w_enc + b_enc); a_sigT scattered store (proven R13)
// ---------------------------------------------------------------------------
__global__ __launch_bounds__(128) void gemm_enc(const float* __restrict__ X,
                                                const float* __restrict__ W,
                                                const float* __restrict__ bias) {
    __shared__ __align__(16) float As[16][68];
    __shared__ __align__(16) float Bs[16][36];
    int t = threadIdx.x;
    if (blockIdx.x == 0 && blockIdx.y == 0 && t < 4) g_acc[t] = 0.f;
    int m0 = blockIdx.y * 64, n0 = blockIdx.x * 32;
    int arow = t >> 2, acol = (t & 3) << 2;
    int brow = t >> 3, bcol = (t & 7) << 2;
    int ry = (t >> 3) << 2, rx = (t & 7) << 2;
    float acc[4][4] = {};
    const float* ap = X + (size_t)m0 * Kk;
    const float* bp = W + n0;
    float4 av0 = *(const float4*)(ap + (size_t)arow * Kk + acol);
    float4 av1 = *(const float4*)(ap + (size_t)(arow + 32) * Kk + acol);
    float4 bv  = *(const float4*)(bp + (size_t)brow * Nn + bcol);
    for (int k0 = 0; k0 < Kk; k0 += 16) {
        __syncthreads();
        As[acol + 0][arow] = av0.x; As[acol + 1][arow] = av0.y;
        As[acol + 2][arow] = av0.z; As[acol + 3][arow] = av0.w;
        As[acol + 0][arow + 32] = av1.x; As[acol + 1][arow + 32] = av1.y;
        As[acol + 2][arow + 32] = av1.z; As[acol + 3][arow + 32] = av1.w;
        *(float4*)(&Bs[brow][bcol]) = bv;
        __syncthreads();
        if (k0 + 16 < Kk) {
            av0 = *(const float4*)(ap + (size_t)arow * Kk + k0 + 16 + acol);
            av1 = *(const float4*)(ap + (size_t)(arow + 32) * Kk + k0 + 16 + acol);
            bv  = *(const float4*)(bp + (size_t)(k0 + 16 + brow) * Nn + bcol);
        }
#pragma unroll
        for (int k = 0; k < 16; k++) {
            float4 a4 = *(float4*)(&As[k][ry]);
            float4 b4 = *(float4*)(&Bs[k][rx]);
            float am[4] = {a4.x, a4.y, a4.z, a4.w};
            float bn[4] = {b4.x, b4.y, b4.z, b4.w};
#pragma unroll
            for (int i = 0; i < 4; i++)
#pragma unroll
                for (int j = 0; j < 4; j++)
                    acc[i][j] = fmaf(am[i], bn[j], acc[i][j]);
        }
    }
    float4 b4 = *(const float4*)(bias + n0 + rx);
    float bb[4] = {b4.x, b4.y, b4.z, b4.w};
#pragma unroll
    for (int i = 0; i < 4; i++) {
        int m = m0 + ry + i;
        float aa[4];
#pragma unroll
        for (int j = 0; j < 4; j++) {
            float v = acc[i][j] + bb[j];
            float a = fmaxf(v, 0.f);
            aa[j] = a;
            float e = __expf(-a);
            g_asigT[(size_t)(n0 + rx + j) * Bb + m] = __fdividef(2.f, 1.f + e) - 1.f;
        }
        *(float4*)(g_a + (size_t)m * Nn + n0 + rx) =
            make_float4(aa[0], aa[1], aa[2], aa[3]);
    }
}

// ---------------------------------------------------------------------------
// dec body (proven R13): x_hat tile + recon partial
// ---------------------------------------------------------------------------
__device__ __forceinline__ void dec_body(int bx, char* shm,
                                         const float* __restrict__ W,
                                         const float* __restrict__ bias,
                                         const float* __restrict__ X,
                                         float* __restrict__ xhat) {
    float (*As)[68] = (float (*)[68])shm;
    float (*Bs)[36] = (float (*)[36])(shm + 4352);
    float* red = (float*)(shm + 6656);
    int t = threadIdx.x;
    int m0 = (bx >> 5) * 64, n0 = (bx & 31) * 32;
    int arow = t >> 2, acol = (t & 3) << 2;
    int brow = t >> 3, bcol = (t & 7) << 2;
    int ry = (t >> 3) << 2, rx = (t & 7) << 2;
    float acc[4][4] = {};
    const float* ap = g_a + (size_t)m0 * Nn;
    const float* bp = W + n0;
    float4 av0 = *(const float4*)(ap + (size_t)arow * Nn + acol);
    float4 av1 = *(const float4*)(ap + (size_t)(arow + 32) * Nn + acol);
    float4 bv  = *(const float4*)(bp + (size_t)brow * Pp + bcol);
    for (int k0 = 0; k0 < Nn; k0 += 16) {
        __syncthreads();
        As[acol + 0][arow] = av0.x; As[acol + 1][arow] = av0.y;
        As[acol + 2][arow] = av0.z; As[acol + 3][arow] = av0.w;
        As[acol + 0][arow + 32] = av1.x; As[acol + 1][arow + 32] = av1.y;
        As[acol + 2][arow + 32] = av1.z; As[acol + 3][arow + 32] = av1.w;
        *(float4*)(&Bs[brow][bcol]) = bv;
        __syncthreads();
        if (k0 + 16 < Nn) {
            av0 = *(const float4*)(ap + (size_t)arow * Nn + k0 + 16 + acol);
            av1 = *(const float4*)(ap + (size_t)(arow + 32) * Nn + k0 + 16 + acol);
            bv  = *(const float4*)(bp + (size_t)(k0 + 16 + brow) * Pp + bcol);
        }
#pragma unroll
        for (int k = 0; k < 16; k++) {
            float4 a4 = *(float4*)(&As[k][ry]);
            float4 b4 = *(float4*)(&Bs[k][rx]);
            float am[4] = {a4.x, a4.y, a4.z, a4.w};
            float bn[4] = {b4.x, b4.y, b4.z, b4.w};
#pragma unroll
            for (int i = 0; i < 4; i++)
#pragma unroll
                for (int j = 0; j < 4; j++)
                    acc[i][j] = fmaf(am[i], bn[j], acc[i][j]);
        }
    }
    float lsum = 0.f;
    float4 b4 = *(const float4*)(bias + n0 + rx);
    float bb[4] = {b4.x, b4.y, b4.z, b4.w};
#pragma unroll
    for (int i = 0; i < 4; i++) {
        int m = m0 + ry + i;
        float4 xv = *(const float4*)(X + (size_t)m * Pp + n0 + rx);
        float xm[4] = {xv.x, xv.y, xv.z, xv.w};
        float vv[4];
#pragma unroll
        for (int j = 0; j < 4; j++) {
            float v = acc[i][j] + bb[j];
            vv[j] = v;
            float d = xm[j] - v;
            lsum = fmaf(d, d, lsum);
        }
        *(float4*)(xhat + (size_t)m * Pp + n0 + rx) =
            make_float4(vv[0], vv[1], vv[2], vv[3]);
    }
#pragma unroll
    for (int o = 16; o > 0; o >>= 1) lsum += __shfl_xor_sync(~0u, lsum, o);
    if ((t & 31) == 0) red[t >> 5] = lsum;
    __syncthreads();
    if (t == 0) atomicAdd(&g_acc[0], red[0] + red[1] + red[2] + red[3]);
}

// ---------------------------------------------------------------------------
// mle body: ONE BLOCK PER NEURON, 4 warps x 128 samples (4/lane).
// Per-warp private G region (4 lane-replicas, 33-padded); one syncthreads
// pair per step for cross-warp G / s_acc totals; theta replicated per warp.
// ---------------------------------------------------------------------------
__device__ __forceinline__ void mle_body(int n, char* shm,
                                         const float* __restrict__ thetas,
                                         const float* __restrict__ centers,
                                         float* __restrict__ ent_out) {
    float (*s_pi)[32] = (float (*)[32])shm;            // 4*32*4   = 512 B
    float (*s_G)[132] = (float (*)[132])(shm + 512);   // 4*132*4  = 2112 B
    float* s_c = (float*)(shm + 2624);                 // 128 B
    float* s_pa = (float*)(shm + 2752);                // 4 partials
    int tid = threadIdx.x;
    int warp = tid >> 5, lane = tid & 31;
    if (tid < 32) s_c[tid] = centers[tid];
    __syncthreads();
    float c0 = s_c[0];
    float invw = __fdividef(1.0f, s_c[1] - s_c[0]);

    // this warp's 128 samples: b = warp*128 + i*32 + lane
    const float* col = g_asigT + (size_t)n * Bb + warp * 128;
    int t0[4];
    float w0[4], w1[4];
    unsigned skip = 0;
    int zc = 0, oc = 0;
#pragma unroll
    for (int i = 0; i < 4; i++) {
        float as = col[i * 32 + lane];
        if (as == 0.f) { skip |= 1u << i; zc++; }
        else if (as == 1.f) { skip |= 1u << i; oc++; }
        float xf = (as - c0) * invw;
        int tt = (int)floorf(xf);
        tt = min(max(tt, 0), 30);
        t0[i] = tt;
        w0[i] = fmaxf(0.f, 1.f - fabsf(as - s_c[tt]) * invw);
        w1[i] = fmaxf(0.f, 1.f - fabsf(as - s_c[tt + 1]) * invw);
    }
    // per-warp cluster counts
    int ztot = zc, otot = oc;
#pragma unroll
    for (int o = 16; o > 0; o >>= 1) {
        ztot += __shfl_xor_sync(~0u, ztot, o);
        otot += __shfl_xor_sync(~0u, otot, o);
    }
    float w0z = fmaxf(0.f, 1.f - fabsf(s_c[15]) * invw);
    float w1z = fmaxf(0.f, 1.f - fabsf(s_c[16]) * invw);
    float w0o = fmaxf(0.f, 1.f - fabsf(1.f - s_c[30]) * invw);
    float w1o = fmaxf(0.f, 1.f - fabsf(1.f - s_c[31]) * invw);
    float zf = (float)ztot, of = (float)otot;

    float th = thetas[n * Tt + lane];
    float* pi = s_pi[warp];
    float* G = s_G[warp];
    int rep = (lane & 3) * 33;

    for (int step = 0; step < 15; step++) {
        // softmax over T=32 (replicated per warp, identical results)
        float m = th;
#pragma unroll
        for (int o = 16; o > 0; o >>= 1) m = fmaxf(m, __shfl_xor_sync(~0u, m, o));
        float e = __expf(th - m);
        float sum = e;
#pragma unroll
        for (int o = 16; o > 0; o >>= 1) sum += __shfl_xor_sync(~0u, sum, o);
        float p_l = __fdividef(e, sum);
        pi[lane] = p_l;
        G[0 * 33 + lane] = 0.f; G[1 * 33 + lane] = 0.f;
        G[2 * 33 + lane] = 0.f; G[3 * 33 + lane] = 0.f;
        __syncwarp();

        float s_acc = 0.f;
        if (lane == 0 && ztot > 0) {
            float pz = w0z * pi[15] + w1z * pi[16];
            float rz = __fdividef(1.f, pz + EPSV);
            atomicAdd(&G[0 * 33 + 15], zf * w0z * rz);
            atomicAdd(&G[0 * 33 + 16], zf * w1z * rz);
            s_acc += zf * pz * rz;
        }
        if (lane == 1 && otot > 0) {
            float po = w0o * pi[30] + w1o * pi[31];
            float ro = __fdividef(1.f, po + EPSV);
            atomicAdd(&G[1 * 33 + 30], of * w0o * ro);
            atomicAdd(&G[1 * 33 + 31], of * w1o * ro);
            s_acc += of * po * ro;
        }
#pragma unroll
        for (int i = 0; i < 4; i++) {
            if (!((skip >> i) & 1u)) {
                float p = w0[i] * pi[t0[i]] + w1[i] * pi[t0[i] + 1];
                float r = __fdividef(1.f, p + EPSV);
                atomicAdd(&G[rep + t0[i]], w0[i] * r);
                atomicAdd(&G[rep + t0[i] + 1], w1[i] * r);
                s_acc = fmaf(p, r, s_acc);
            }
        }
#pragma unroll
        for (int o = 16; o > 0; o >>= 1) s_acc += __shfl_xor_sync(~0u, s_acc, o);
        if (lane == 0) s_pa[warp] = s_acc;
        __syncthreads();
        // totals across all 4 warps (identical in every warp)
        float gt = 0.f;
#pragma unroll
        for (int w2 = 0; w2 < 4; w2++) {
            float* Gw = s_G[w2];
            gt += Gw[0 * 33 + lane] + Gw[1 * 33 + lane] +
                  Gw[2 * 33 + lane] + Gw[3 * 33 + lane];
        }
        float st = s_pa[0] + s_pa[1] + s_pa[2] + s_pa[3];
        th += 0.01f * (p_l * (gt - st));
        __syncthreads();
    }

    // final softmax + entropy
    float m = th;
#pragma unroll
    for (int o = 16; o > 0; o >>= 1) m = fmaxf(m, __shfl_xor_sync(~0u, m, o));
    float e = __expf(th - m);
    float sum = e;
#pragma unroll
    for (int o = 16; o > 0; o >>= 1) sum += __shfl_xor_sync(~0u, sum, o);
    pi[lane] = __fdividef(e, sum);
    __syncwarp();

    float ent = 0.f;
    if (lane == 0 && ztot > 0) {
        float pz = w0z * pi[15] + w1z * pi[16];
        ent -= zf * pz * __logf(pz + EPSV);
    }
    if (lane == 1 && otot > 0) {
        float po = w0o * pi[30] + w1o * pi[31];
        ent -= of * po * __logf(po + EPSV);
    }
#pragma unroll
    for (int i = 0; i < 4; i++) {
        if (!((skip >> i) & 1u)) {
            float p = w0[i] * pi[t0[i]] + w1[i] * pi[t0[i] + 1];
            ent -= p * __logf(p + EPSV);
        }
    }
#pragma unroll
    for (int o = 16; o > 0; o >>= 1) ent += __shfl_xor_sync(~0u, ent, o);
    if (lane == 0) s_pa[warp] = ent;
    __syncthreads();
    if (tid == 0) {
        float et = s_pa[0] + s_pa[1] + s_pa[2] + s_pa[3];
        ent_out[n] = et;
        atomicAdd(&g_acc[1], et);
    }
}

__device__ __forceinline__ void decay_body(int bx, char* shm,
                                           const float* __restrict__ we,
                                           const float* __restrict__ wd) {
    float* red = (float*)shm;
    float s = 0.f;
    const float4* we4 = (const float4*)we;
    const float4* wd4 = (const float4*)wd;
    int nv = (Nn * Pp) / 4;
    for (int i = bx * 128 + threadIdx.x; i < nv; i += DECAY_BLOCKS * 128) {
        float4 a = we4[i];
        s = fmaf(a.x, a.x, s); s = fmaf(a.y, a.y, s);
        s = fmaf(a.z, a.z, s); s = fmaf(a.w, a.w, s);
        float4 b = wd4[i];
        s = fmaf(b.x, b.x, s); s = fmaf(b.y, b.y, s);
        s = fmaf(b.z, b.z, s); s = fmaf(b.w, b.w, s);
    }
#pragma unroll
    for (int o = 16; o > 0; o >>= 1) s += __shfl_xor_sync(~0u, s, o);
    if ((threadIdx.x & 31) == 0) red[threadIdx.x >> 5] = s;
    __syncthreads();
    if (threadIdx.x == 0)
        atomicAdd(&g_acc[2], red[0] + red[1] + red[2] + red[3]);
}

// ---------------------------------------------------------------------------
// phase2: fused dec-GEMM + MLE + decay
// ---------------------------------------------------------------------------
__global__ __launch_bounds__(128) void phase2(const float* __restrict__ wd,
                                              const float* __restrict__ bd,
                                              const float* __restrict__ x,
                                              float* __restrict__ xhat,
                                              const float* __restrict__ thetas,
                                              const float* __restrict__ centers,
                                              float* __restrict__ ent_out,
                                              const float* __restrict__ we) {
    __shared__ __align__(16) char shm[6784];
    int bx = blockIdx.x;
    if (bx < DEC_BLOCKS) {
        dec_body(bx, shm, wd, bd, x, xhat);
    } else if (bx < DEC_BLOCKS + MLE_BLOCKS) {
        mle_body(bx - DEC_BLOCKS, shm, thetas, centers, ent_out);
    } else {
        decay_body(bx - DEC_BLOCKS - MLE_BLOCKS, shm, we, wd);
    }
}

__global__ void finalize_kernel(float* __restrict__ out) {
    out[Bb * Pp + Nn] = (0.5f / (float)Bb) * g_acc[0] + 0.01f * g_acc[1] +
                        0.00025f * g_acc[2];
}

extern "C" void kernel_launch(void* const* d_in, const int* in_sizes, int n_in,
                              void* d_out, int out_size) {
    const float* x   = (const float*)d_in[0];
    const float* we  = (const float*)d_in[1];
    const float* be  = (const float*)d_in[2];
    const float* wd  = (const float*)d_in[3];
    const float* bd  = (const float*)d_in[4];
    const float* th  = (const float*)d_in[5];
    const float* cen = (const float*)d_in[6];
    float* out = (float*)d_out;

    gemm_enc<<<dim3(Nn / 32, Bb / 64), 128>>>(x, we, be);
    phase2<<<PH2_BLOCKS, 128>>>(wd, bd, x, out, th, cen, out + Bb * Pp, we);
    finalize_kernel<<<1, 1>>>(out);
}

// round 15
// speedup vs baseline: 1.6958x; 1.1155x over previous
#include <cuda_runtime.h>
#include <stdint.h>
#include <math.h>

#define Bb 512
#define Nn 1024
#define Pp 1024
#define Kk 1024
#define Tt 32
#define EPSV 1e-10f

#define MLE_BLOCKS 1024   // one block per neuron (FIRST: latency-critical)
#define DEC_BLOCKS 256    // (Pp/32) * (Bb/64)
#define DECAY_BLOCKS 64
#define PH2_BLOCKS (MLE_BLOCKS + DEC_BLOCKS + DECAY_BLOCKS)

// scratch (no allocations allowed)
__device__ float g_a[Bb * Nn];      // relu activations [B,N]
__device__ float g_asigT[Nn * Bb];  // sigmoid activations, transposed [N,B]
__device__ float g_acc[4];          // 0: recon sq-sum, 1: entropy, 2: decay

// ---------------------------------------------------------------------------
// GEMM1: a = relu(x @ w_enc + b_enc); a_sigT scattered store (proven R14)
// ---------------------------------------------------------------------------
__global__ __launch_bounds__(128) void gemm_enc(const float* __restrict__ X,
                                                const float* __restrict__ W,
                                                const float* __restrict__ bias) {
    __shared__ __align__(16) float As[16][68];
    __shared__ __align__(16) float Bs[16][36];
    int t = threadIdx.x;
    if (blockIdx.x == 0 && blockIdx.y == 0 && t < 4) g_acc[t] = 0.f;
    int m0 = blockIdx.y * 64, n0 = blockIdx.x * 32;
    int arow = t >> 2, acol = (t & 3) << 2;
    int brow = t >> 3, bcol = (t & 7) << 2;
    int ry = (t >> 3) << 2, rx = (t & 7) << 2;
    float acc[4][4] = {};
    const float* ap = X + (size_t)m0 * Kk;
    const float* bp = W + n0;
    float4 av0 = *(const float4*)(ap + (size_t)arow * Kk + acol);
    float4 av1 = *(const float4*)(ap + (size_t)(arow + 32) * Kk + acol);
    float4 bv  = *(const float4*)(bp + (size_t)brow * Nn + bcol);
    for (int k0 = 0; k0 < Kk; k0 += 16) {
        __syncthreads();
        As[acol + 0][arow] = av0.x; As[acol + 1][arow] = av0.y;
        As[acol + 2][arow] = av0.z; As[acol + 3][arow] = av0.w;
        As[acol + 0][arow + 32] = av1.x; As[acol + 1][arow + 32] = av1.y;
        As[acol + 2][arow + 32] = av1.z; As[acol + 3][arow + 32] = av1.w;
        *(float4*)(&Bs[brow][bcol]) = bv;
        __syncthreads();
        if (k0 + 16 < Kk) {
            av0 = *(const float4*)(ap + (size_t)arow * Kk + k0 + 16 + acol);
            av1 = *(const float4*)(ap + (size_t)(arow + 32) * Kk + k0 + 16 + acol);
            bv  = *(const float4*)(bp + (size_t)(k0 + 16 + brow) * Nn + bcol);
        }
#pragma unroll
        for (int k = 0; k < 16; k++) {
            float4 a4 = *(float4*)(&As[k][ry]);
            float4 b4 = *(float4*)(&Bs[k][rx]);
            float am[4] = {a4.x, a4.y, a4.z, a4.w};
            float bn[4] = {b4.x, b4.y, b4.z, b4.w};
#pragma unroll
            for (int i = 0; i < 4; i++)
#pragma unroll
                for (int j = 0; j < 4; j++)
                    acc[i][j] = fmaf(am[i], bn[j], acc[i][j]);
        }
    }
    float4 b4 = *(const float4*)(bias + n0 + rx);
    float bb[4] = {b4.x, b4.y, b4.z, b4.w};
#pragma unroll
    for (int i = 0; i < 4; i++) {
        int m = m0 + ry + i;
        float aa[4];
#pragma unroll
        for (int j = 0; j < 4; j++) {
            float v = acc[i][j] + bb[j];
            float a = fmaxf(v, 0.f);
            aa[j] = a;
            float e = __expf(-a);
            g_asigT[(size_t)(n0 + rx + j) * Bb + m] = __fdividef(2.f, 1.f + e) - 1.f;
        }
        *(float4*)(g_a + (size_t)m * Nn + n0 + rx) =
            make_float4(aa[0], aa[1], aa[2], aa[3]);
    }
}

// ---------------------------------------------------------------------------
// dec body (unchanged, proven)
// ---------------------------------------------------------------------------
__device__ __forceinline__ void dec_body(int bx, char* shm,
                                         const float* __restrict__ W,
                                         const float* __restrict__ bias,
                                         const float* __restrict__ X,
                                         float* __restrict__ xhat) {
    float (*As)[68] = (float (*)[68])shm;
    float (*Bs)[36] = (float (*)[36])(shm + 4352);
    float* red = (float*)(shm + 6656);
    int t = threadIdx.x;
    int m0 = (bx >> 5) * 64, n0 = (bx & 31) * 32;
    int arow = t >> 2, acol = (t & 3) << 2;
    int brow = t >> 3, bcol = (t & 7) << 2;
    int ry = (t >> 3) << 2, rx = (t & 7) << 2;
    float acc[4][4] = {};
    const float* ap = g_a + (size_t)m0 * Nn;
    const float* bp = W + n0;
    float4 av0 = *(const float4*)(ap + (size_t)arow * Nn + acol);
    float4 av1 = *(const float4*)(ap + (size_t)(arow + 32) * Nn + acol);
    float4 bv  = *(const float4*)(bp + (size_t)brow * Pp + bcol);
    for (int k0 = 0; k0 < Nn; k0 += 16) {
        __syncthreads();
        As[acol + 0][arow] = av0.x; As[acol + 1][arow] = av0.y;
        As[acol + 2][arow] = av0.z; As[acol + 3][arow] = av0.w;
        As[acol + 0][arow + 32] = av1.x; As[acol + 1][arow + 32] = av1.y;
        As[acol + 2][arow + 32] = av1.z; As[acol + 3][arow + 32] = av1.w;
        *(float4*)(&Bs[brow][bcol]) = bv;
        __syncthreads();
        if (k0 + 16 < Nn) {
            av0 = *(const float4*)(ap + (size_t)arow * Nn + k0 + 16 + acol);
            av1 = *(const float4*)(ap + (size_t)(arow + 32) * Nn + k0 + 16 + acol);
            bv  = *(const float4*)(bp + (size_t)(k0 + 16 + brow) * Pp + bcol);
        }
#pragma unroll
        for (int k = 0; k < 16; k++) {
            float4 a4 = *(float4*)(&As[k][ry]);
            float4 b4 = *(float4*)(&Bs[k][rx]);
            float am[4] = {a4.x, a4.y, a4.z, a4.w};
            float bn[4] = {b4.x, b4.y, b4.z, b4.w};
#pragma unroll
            for (int i = 0; i < 4; i++)
#pragma unroll
                for (int j = 0; j < 4; j++)
                    acc[i][j] = fmaf(am[i], bn[j], acc[i][j]);
        }
    }
    float lsum = 0.f;
    float4 b4 = *(const float4*)(bias + n0 + rx);
    float bb[4] = {b4.x, b4.y, b4.z, b4.w};
#pragma unroll
    for (int i = 0; i < 4; i++) {
        int m = m0 + ry + i;
        float4 xv = *(const float4*)(X + (size_t)m * Pp + n0 + rx);
        float xm[4] = {xv.x, xv.y, xv.z, xv.w};
        float vv[4];
#pragma unroll
        for (int j = 0; j < 4; j++) {
            float v = acc[i][j] + bb[j];
            vv[j] = v;
            float d = xm[j] - v;
            lsum = fmaf(d, d, lsum);
        }
        *(float4*)(xhat + (size_t)m * Pp + n0 + rx) =
            make_float4(vv[0], vv[1], vv[2], vv[3]);
    }
#pragma unroll
    for (int o = 16; o > 0; o >>= 1) lsum += __shfl_xor_sync(~0u, lsum, o);
    if ((t & 31) == 0) red[t >> 5] = lsum;
    __syncthreads();
    if (t == 0) atomicAdd(&g_acc[0], red[0] + red[1] + red[2] + red[3]);
}

// ---------------------------------------------------------------------------
// mle body: one block/neuron, 4 warps x 4 samples/lane.
// ONE __syncthreads per step: G and s_pa are parity double-buffered (the only
// cross-warp-read structures); pi is warp-private (syncwarp-protected).
// ---------------------------------------------------------------------------
__device__ __forceinline__ void mle_body(int n, char* shm,
                                         const float* __restrict__ thetas,
                                         const float* __restrict__ centers,
                                         float* __restrict__ ent_out) {
    float (*s_pi)[32] = (float (*)[32])shm;                  // 512 B
    float (*s_G)[4][132] = (float (*)[4][132])(shm + 512);   // 2*4*132*4 = 4224 B
    float* s_c = (float*)(shm + 4736);                       // 128 B
    float (*s_pa)[4] = (float (*)[4])(shm + 4864);           // 32 B
    int tid = threadIdx.x;
    int warp = tid >> 5, lane = tid & 31;
    if (tid < 32) s_c[tid] = centers[tid];
    __syncthreads();
    float c0 = s_c[0];
    float invw = __fdividef(1.0f, s_c[1] - s_c[0]);

    const float* col = g_asigT + (size_t)n * Bb + warp * 128;
    int t0[4];
    float w0[4], w1[4];
    unsigned skip = 0;
    int zc = 0, oc = 0;
#pragma unroll
    for (int i = 0; i < 4; i++) {
        float as = col[i * 32 + lane];
        if (as == 0.f) { skip |= 1u << i; zc++; }
        else if (as == 1.f) { skip |= 1u << i; oc++; }
        float xf = (as - c0) * invw;
        int tt = (int)floorf(xf);
        tt = min(max(tt, 0), 30);
        t0[i] = tt;
        w0[i] = fmaxf(0.f, 1.f - fabsf(as - s_c[tt]) * invw);
        w1[i] = fmaxf(0.f, 1.f - fabsf(as - s_c[tt + 1]) * invw);
    }
    int ztot = zc, otot = oc;
#pragma unroll
    for (int o = 16; o > 0; o >>= 1) {
        ztot += __shfl_xor_sync(~0u, ztot, o);
        otot += __shfl_xor_sync(~0u, otot, o);
    }
    float w0z = fmaxf(0.f, 1.f - fabsf(s_c[15]) * invw);
    float w1z = fmaxf(0.f, 1.f - fabsf(s_c[16]) * invw);
    float w0o = fmaxf(0.f, 1.f - fabsf(1.f - s_c[30]) * invw);
    float w1o = fmaxf(0.f, 1.f - fabsf(1.f - s_c[31]) * invw);
    float zf = (float)ztot, of = (float)otot;

    float th = thetas[n * Tt + lane];
    float* pi = s_pi[warp];
    int rep = (lane & 3) * 33;

    for (int step = 0; step < 15; step++) {
        int bsel = step & 1;
        float* G = s_G[bsel][warp];
        // softmax over T=32 (replicated per warp, identical results)
        float m = th;
#pragma unroll
        for (int o = 16; o > 0; o >>= 1) m = fmaxf(m, __shfl_xor_sync(~0u, m, o));
        float e = __expf(th - m);
        float sum = e;
#pragma unroll
        for (int o = 16; o > 0; o >>= 1) sum += __shfl_xor_sync(~0u, sum, o);
        float p_l = __fdividef(e, sum);
        pi[lane] = p_l;
        G[0 * 33 + lane] = 0.f; G[1 * 33 + lane] = 0.f;
        G[2 * 33 + lane] = 0.f; G[3 * 33 + lane] = 0.f;
        __syncwarp();

        float s_acc = 0.f;
        if (lane == 0 && ztot > 0) {
            float pz = w0z * pi[15] + w1z * pi[16];
            float rz = __fdividef(1.f, pz + EPSV);
            atomicAdd(&G[0 * 33 + 15], zf * w0z * rz);
            atomicAdd(&G[0 * 33 + 16], zf * w1z * rz);
            s_acc += zf * pz * rz;
        }
        if (lane == 1 && otot > 0) {
            float po = w0o * pi[30] + w1o * pi[31];
            float ro = __fdividef(1.f, po + EPSV);
            atomicAdd(&G[1 * 33 + 30], of * w0o * ro);
            atomicAdd(&G[1 * 33 + 31], of * w1o * ro);
            s_acc += of * po * ro;
        }
#pragma unroll
        for (int i = 0; i < 4; i++) {
            if (!((skip >> i) & 1u)) {
                float p = w0[i] * pi[t0[i]] + w1[i] * pi[t0[i] + 1];
                float r = __fdividef(1.f, p + EPSV);
                atomicAdd(&G[rep + t0[i]], w0[i] * r);
                atomicAdd(&G[rep + t0[i] + 1], w1[i] * r);
                s_acc = fmaf(p, r, s_acc);
            }
        }
#pragma unroll
        for (int o = 16; o > 0; o >>= 1) s_acc += __shfl_xor_sync(~0u, s_acc, o);
        if (lane == 0) s_pa[bsel][warp] = s_acc;
        __syncthreads();
        float gt = 0.f;
#pragma unroll
        for (int w2 = 0; w2 < 4; w2++) {
            const float* Gw = s_G[bsel][w2];
            gt += Gw[0 * 33 + lane] + Gw[1 * 33 + lane] +
                  Gw[2 * 33 + lane] + Gw[3 * 33 + lane];
        }
        float st = s_pa[bsel][0] + s_pa[bsel][1] + s_pa[bsel][2] + s_pa[bsel][3];
        th += 0.01f * (p_l * (gt - st));
        // no second barrier: next step writes parity bsel^1; re-use of parity
        // bsel is separated by the next step's barrier (two-step argument)
    }

    // final softmax + entropy (pi warp-private; partials in parity-1 buffer,
    // whose last cross-warp read was step 13, sealed by step 14's barrier)
    float m = th;
#pragma unroll
    for (int o = 16; o > 0; o >>= 1) m = fmaxf(m, __shfl_xor_sync(~0u, m, o));
    float e = __expf(th - m);
    float sum = e;
#pragma unroll
    for (int o = 16; o > 0; o >>= 1) sum += __shfl_xor_sync(~0u, sum, o);
    pi[lane] = __fdividef(e, sum);
    __syncwarp();

    float ent = 0.f;
    if (lane == 0 && ztot > 0) {
        float pz = w0z * pi[15] + w1z * pi[16];
        ent -= zf * pz * __logf(pz + EPSV);
    }
    if (lane == 1 && otot > 0) {
        float po = w0o * pi[30] + w1o * pi[31];
        ent -= of * po * __logf(po + EPSV);
    }
#pragma unroll
    for (int i = 0; i < 4; i++) {
        if (!((skip >> i) & 1u)) {
            float p = w0[i] * pi[t0[i]] + w1[i] * pi[t0[i] + 1];
            ent -= p * __logf(p + EPSV);
        }
    }
#pragma unroll
    for (int o = 16; o > 0; o >>= 1) ent += __shfl_xor_sync(~0u, ent, o);
    if (lane == 0) s_pa[1][warp] = ent;
    __syncthreads();
    if (tid == 0) {
        float et = s_pa[1][0] + s_pa[1][1] + s_pa[1][2] + s_pa[1][3];
        ent_out[n] = et;
        atomicAdd(&g_acc[1], et);
    }
}

__device__ __forceinline__ void decay_body(int bx, char* shm,
                                           const float* __restrict__ we,
                                           const float* __restrict__ wd) {
    float* red = (float*)shm;
    float s = 0.f;
    const float4* we4 = (const float4*)we;
    const float4* wd4 = (const float4*)wd;
    int nv = (Nn * Pp) / 4;
    for (int i = bx * 128 + threadIdx.x; i < nv; i += DECAY_BLOCKS * 128) {
        float4 a = we4[i];
        s = fmaf(a.x, a.x, s); s = fmaf(a.y, a.y, s);
        s = fmaf(a.z, a.z, s); s = fmaf(a.w, a.w, s);
        float4 b = wd4[i];
        s = fmaf(b.x, b.x, s); s = fmaf(b.y, b.y, s);
        s = fmaf(b.z, b.z, s); s = fmaf(b.w, b.w, s);
    }
#pragma unroll
    for (int o = 16; o > 0; o >>= 1) s += __shfl_xor_sync(~0u, s, o);
    if ((threadIdx.x & 31) == 0) red[threadIdx.x >> 5] = s;
    __syncthreads();
    if (threadIdx.x == 0)
        atomicAdd(&g_acc[2], red[0] + red[1] + red[2] + red[3]);
}

// ---------------------------------------------------------------------------
// phase2: MLE blocks FIRST (latency-critical chains start at t=0), then
// dec-GEMM, then decay
// ---------------------------------------------------------------------------
__global__ __launch_bounds__(128) void phase2(const float* __restrict__ wd,
                                              const float* __restrict__ bd,
                                              const float* __restrict__ x,
                                              float* __restrict__ xhat,
                                              const float* __restrict__ thetas,
                                              const float* __restrict__ centers,
                                              float* __restrict__ ent_out,
                                              const float* __restrict__ we) {
    __shared__ __align__(16) char shm[6784];
    int bx = blockIdx.x;
    if (bx < MLE_BLOCKS) {
        mle_body(bx, shm, thetas, centers, ent_out);
    } else if (bx < MLE_BLOCKS + DEC_BLOCKS) {
        dec_body(bx - MLE_BLOCKS, shm, wd, bd, x, xhat);
    } else {
        decay_body(bx - MLE_BLOCKS - DEC_BLOCKS, shm, we, wd);
    }
}

__global__ void finalize_kernel(float* __restrict__ out) {
    out[Bb * Pp + Nn] = (0.5f / (float)Bb) * g_acc[0] + 0.01f * g_acc[1] +
                        0.00025f * g_acc[2];
}

extern "C" void kernel_launch(void* const* d_in, const int* in_sizes, int n_in,
                              void* d_out, int out_size) {
    const float* x   = (const float*)d_in[0];
    const float* we  = (const float*)d_in[1];
    const float* be  = (const float*)d_in[2];
    const float* wd  = (const float*)d_in[3];
    const float* bd  = (const float*)d_in[4];
    const float* th  = (const float*)d_in[5];
    const float* cen = (const float*)d_in[6];
    float* out = (float*)d_out;

    gemm_enc<<<dim3(Nn / 32, Bb / 64), 128>>>(x, we, be);
    phase2<<<PH2_BLOCKS, 128>>>(wd, bd, x, out, th, cen, out + Bb * Pp, we);
    finalize_kernel<<<1, 1>>>(out);
}